// round 6
// baseline (speedup 1.0000x reference)
#include <cuda_runtime.h>
#include <cuda_fp16.h>
#include <mma.h>
#include <cstdint>

using namespace nvcuda;

#define D_MODEL     2048
#define NUM_CLASSES 50257
#define NB          8
#define RANK        4
#define HIDDEN      128
#define BATCH       2048
#define LN_EPS      1e-5f

#define KTOT   2112                 // 2048 (x|w) + 32 (LoRA u|Bt) + 32 zero pad
#define BK     64
#define NST    (KTOT / BK)          // 33 stages, single fp16 pass

#define BM 128
#define BN 128
#define LDSH 72                     // fp16 elems per smem row (144B)
#define TILE_ELEMS (128 * LDSH)
#define TILE_BYTES (TILE_ELEMS * 2)         // 18432 per A or B tile
#define STAGE_BYTES (2 * TILE_BYTES)        // 36864
#define SMEM_TOTAL  (2 * STAGE_BYTES)       // 73728 B

// prep_ctx dynamic smem layout (floats)
#define P_WSH   0
#define P_XSH   (128 * 129)
#define P_HSH   (P_XSH + 16 * 129)
#define P_YSH   (P_HSH + 16 * 128)
#define P_CSH   (P_YSH + 16 * 32)
#define P_ZSH   (P_CSH + 16 * 8)
#define P_TOTAL (P_ZSH + 16 * 4)

// ---------------- device scratch ----------------
__device__ float  g_u[BATCH * 32];
__device__ __half g_Xh[(size_t)BATCH       * KTOT];
__device__ __half g_Wh[(size_t)NUM_CLASSES * KTOT];

__device__ __forceinline__ uint32_t smem_u32(const void* p) {
    uint32_t a;
    asm("{ .reg .u64 t; cvta.to.shared.u64 t, %1; cvt.u32.u64 %0, t; }" : "=r"(a) : "l"(p));
    return a;
}
#define CP_ASYNC16(dst, src) \
    asm volatile("cp.async.cg.shared.global [%0], [%1], 16;" :: "r"(dst), "l"(src))
#define CP_COMMIT() asm volatile("cp.async.commit_group;" ::: "memory")
#define CP_WAIT(n)  asm volatile("cp.async.wait_group %0;" :: "n"(n) : "memory")

// ---------------------------------------------------------------------------
// prep_ctx (coalesced): ctx MLP -> LN -> GELU -> coeffs -> z -> u
// ---------------------------------------------------------------------------
__global__ __launch_bounds__(256) void prep_ctx(
    const float* __restrict__ x, const float* __restrict__ context,
    const float* __restrict__ ctx_w, const float* __restrict__ ctx_b,
    const float* __restrict__ ln_g, const float* __restrict__ ln_b,
    const float* __restrict__ coeff_w, const float* __restrict__ coeff_b,
    const float* __restrict__ basis_A)
{
    extern __shared__ float ps[];
    float* wsh = ps + P_WSH;
    float* xsh = ps + P_XSH;
    float* hsh = ps + P_HSH;
    float* ysh = ps + P_YSH;
    float* csh = ps + P_CSH;
    float* zsh = ps + P_ZSH;

    const int t  = threadIdx.x;
    const int r0 = blockIdx.x * 16;

    // Phase A: h0 = context @ ctx_w^T + ctx_b
    {
        const int hA    = t & 127;
        const int rhalf = t >> 7;
        float acc[8];
        #pragma unroll
        for (int r = 0; r < 8; r++) acc[r] = 0.f;

        #pragma unroll 1
        for (int kc = 0; kc < D_MODEL / 128; kc++) {
            #pragma unroll
            for (int i = 0; i < 16; i++) {
                int idx = t + 256 * i;
                int h = idx >> 5, kq = idx & 31;
                float4 v = *reinterpret_cast<const float4*>(
                    ctx_w + (size_t)h * D_MODEL + kc * 128 + kq * 4);
                float* d = wsh + h * 129 + kq * 4;
                d[0] = v.x; d[1] = v.y; d[2] = v.z; d[3] = v.w;
            }
            #pragma unroll
            for (int i = 0; i < 8; i++) {
                int idx = t + 256 * i;
                int r = idx >> 7, k = idx & 127;
                xsh[r * 129 + k] = context[(size_t)(r0 + r) * D_MODEL + kc * 128 + k];
            }
            __syncthreads();
            #pragma unroll 4
            for (int k = 0; k < 128; k++) {
                float w = wsh[hA * 129 + k];
                #pragma unroll
                for (int r = 0; r < 8; r++)
                    acc[r] += xsh[(rhalf * 8 + r) * 129 + k] * w;
            }
            __syncthreads();
        }
        float b = ctx_b[hA];
        #pragma unroll
        for (int r = 0; r < 8; r++)
            hsh[(rhalf * 8 + r) * 128 + hA] = acc[r] + b;
    }
    __syncthreads();

    // Phase B: LayerNorm + exact GELU
    {
        const int lane = t & 31, w = t >> 5;
        #pragma unroll
        for (int rr = 0; rr < 2; rr++) {
            int row = w * 2 + rr;
            float v[4]; float s = 0.f;
            #pragma unroll
            for (int j = 0; j < 4; j++) { v[j] = hsh[row * 128 + lane * 4 + j]; s += v[j]; }
            #pragma unroll
            for (int o = 16; o > 0; o >>= 1) s += __shfl_xor_sync(0xffffffffu, s, o);
            float mu = s * (1.0f / HIDDEN);
            float q = 0.f;
            #pragma unroll
            for (int j = 0; j < 4; j++) { float d = v[j] - mu; q += d * d; }
            #pragma unroll
            for (int o = 16; o > 0; o >>= 1) q += __shfl_xor_sync(0xffffffffu, q, o);
            float rstd = rsqrtf(q * (1.0f / HIDDEN) + LN_EPS);
            #pragma unroll
            for (int j = 0; j < 4; j++) {
                int c = lane * 4 + j;
                float hn = (v[j] - mu) * rstd * ln_g[c] + ln_b[c];
                hsh[row * 128 + c] = 0.5f * hn * (1.0f + erff(hn * 0.7071067811865475f));
            }
        }
    }
    __syncthreads();

    // Phase C: coeffs
    if (t < 128) {
        int row = t >> 3, n = t & 7;
        const float* wp = coeff_w + (size_t)n * HIDDEN;
        float acc = coeff_b[n];
        #pragma unroll 8
        for (int j = 0; j < HIDDEN; j++) acc += hsh[row * 128 + j] * wp[j];
        csh[row * 8 + n] = acc;
    }
    __syncthreads();

    // Phase D: y = x @ basis_A^T
    {
        const int ka = t & 31;
        const int rq = t >> 5;
        float acc0 = 0.f, acc1 = 0.f;

        #pragma unroll 1
        for (int kc = 0; kc < D_MODEL / 128; kc++) {
            #pragma unroll
            for (int i = 0; i < 4; i++) {
                int idx = t + 256 * i;
                int a = idx >> 5, kq = idx & 31;
                float4 v = *reinterpret_cast<const float4*>(
                    basis_A + (size_t)a * D_MODEL + kc * 128 + kq * 4);
                float* d = wsh + a * 129 + kq * 4;
                d[0] = v.x; d[1] = v.y; d[2] = v.z; d[3] = v.w;
            }
            #pragma unroll
            for (int i = 0; i < 8; i++) {
                int idx = t + 256 * i;
                int r = idx >> 7, k = idx & 127;
                xsh[r * 129 + k] = x[(size_t)(r0 + r) * D_MODEL + kc * 128 + k];
            }
            __syncthreads();
            #pragma unroll 4
            for (int k = 0; k < 128; k++) {
                float a = wsh[ka * 129 + k];
                acc0 += xsh[(rq * 2 + 0) * 129 + k] * a;
                acc1 += xsh[(rq * 2 + 1) * 129 + k] * a;
            }
            __syncthreads();
        }
        ysh[(rq * 2 + 0) * 32 + ka] = acc0;
        ysh[(rq * 2 + 1) * 32 + ka] = acc1;
    }
    __syncthreads();

    // Phase E: z
    if (t < 64) {
        int row = t >> 2, r = t & 3;
        float acc = 0.f;
        #pragma unroll
        for (int n = 0; n < NB; n++) acc += csh[row * 8 + n] * ysh[row * 32 + n * RANK + r];
        zsh[row * 4 + r] = acc;
    }
    __syncthreads();

    // Phase F: u
    #pragma unroll
    for (int i = 0; i < 2; i++) {
        int idx = t + 256 * i;
        int row = idx >> 5, k = idx & 31;
        g_u[(size_t)(r0 + row) * 32 + k] = csh[row * 8 + (k >> 2)] * zsh[row * 4 + (k & 3)];
    }
}

// ---------------------------------------------------------------------------
__global__ __launch_bounds__(256) void convert_x(const float* __restrict__ x)
{
    size_t i = (size_t)blockIdx.x * 256 + threadIdx.x;
    if (i >= (size_t)BATCH * (KTOT / 8)) return;
    int row = (int)(i / (KTOT / 8));
    int k0  = (int)(i % (KTOT / 8)) * 8;

    float v[8];
    if (k0 < D_MODEL) {
        const float4* p = reinterpret_cast<const float4*>(x + (size_t)row * D_MODEL + k0);
        float4 a = p[0], b = p[1];
        v[0]=a.x; v[1]=a.y; v[2]=a.z; v[3]=a.w; v[4]=b.x; v[5]=b.y; v[6]=b.z; v[7]=b.w;
    } else if (k0 < D_MODEL + 32) {
        #pragma unroll
        for (int j = 0; j < 8; j++) v[j] = g_u[(size_t)row * 32 + (k0 - D_MODEL) + j];
    } else {
        #pragma unroll
        for (int j = 0; j < 8; j++) v[j] = 0.f;
    }
    union { __half h[8]; uint4 u; } H;
    #pragma unroll
    for (int j = 0; j < 8; j++) H.h[j] = __float2half_rn(v[j]);
    *reinterpret_cast<uint4*>(&g_Xh[(size_t)row * KTOT + k0]) = H.u;
}

__global__ __launch_bounds__(256) void convert_w(
    const float* __restrict__ base_w, const float* __restrict__ basis_B)
{
    size_t i = (size_t)blockIdx.x * 256 + threadIdx.x;
    if (i >= (size_t)NUM_CLASSES * (KTOT / 8)) return;
    int row = (int)(i / (KTOT / 8));
    int k0  = (int)(i % (KTOT / 8)) * 8;

    float v[8];
    if (k0 < D_MODEL) {
        const float4* p = reinterpret_cast<const float4*>(base_w + (size_t)row * D_MODEL + k0);
        float4 a = p[0], b = p[1];
        v[0]=a.x; v[1]=a.y; v[2]=a.z; v[3]=a.w; v[4]=b.x; v[5]=b.y; v[6]=b.z; v[7]=b.w;
    } else if (k0 < D_MODEL + 32) {
        #pragma unroll
        for (int j = 0; j < 8; j++) {
            int k = (k0 - D_MODEL) + j;      // n*RANK + r
            v[j] = basis_B[(((size_t)(k >> 2)) * NUM_CLASSES + row) * RANK + (k & 3)];
        }
    } else {
        #pragma unroll
        for (int j = 0; j < 8; j++) v[j] = 0.f;
    }
    union { __half h[8]; uint4 u; } H;
    #pragma unroll
    for (int j = 0; j < 8; j++) H.h[j] = __float2half_rn(v[j]);
    *reinterpret_cast<uint4*>(&g_Wh[(size_t)row * KTOT + k0]) = H.u;
}

// ---------------------------------------------------------------------------
// Main GEMM: out[b][c] = Xh[b]·Wh[c] + base_b[c]
// 128x128 block tile, 4 warps of 64x64 each, BK=64, 2-stage cp.async pipeline.
// ~200 regs/thread, 2 CTAs/SM (RF-bound by design).
// ---------------------------------------------------------------------------
__global__ __launch_bounds__(128, 2) void main_gemm(
    const float* __restrict__ base_b, float* __restrict__ out)
{
    extern __shared__ __align__(128) __half smem[];
    const uint32_t sbase = smem_u32(smem);

    const int t    = threadIdx.x;
    const int warp = t >> 5;       // 0..3
    const int lane = t & 31;
    const int b0   = blockIdx.x * BM;
    const int c0   = blockIdx.y * BN;

    const int wr = warp >> 1;      // 0..1 -> rows wr*64
    const int wc = warp & 1;       // 0..1 -> cols wc*64

    auto issue = [&](int s) {
        if (s >= NST) return;
        int k0 = s * BK;
        const __half* Ag = g_Xh + (size_t)b0 * KTOT + k0;
        int slot = s & 1;
        uint32_t abase = sbase + slot * STAGE_BYTES;
        uint32_t bbase = abase + TILE_BYTES;
        #pragma unroll
        for (int i = 0; i < 8; i++) {
            int idx = t + 128 * i;       // 0..1023
            int r = idx >> 3, c = idx & 7;
            CP_ASYNC16(abase + (uint32_t)(r * LDSH + c * 8) * 2,
                       Ag + (size_t)r * KTOT + c * 8);
            int gr = c0 + r; if (gr > NUM_CLASSES - 1) gr = NUM_CLASSES - 1;
            CP_ASYNC16(bbase + (uint32_t)(r * LDSH + c * 8) * 2,
                       g_Wh + (size_t)gr * KTOT + k0 + c * 8);
        }
        CP_COMMIT();
    };

    wmma::fragment<wmma::accumulator, 16, 16, 16, float> acc[4][4];
    #pragma unroll
    for (int i = 0; i < 4; i++)
        #pragma unroll
        for (int j = 0; j < 4; j++)
            wmma::fill_fragment(acc[i][j], 0.0f);

    issue(0); issue(1);

    #pragma unroll 1
    for (int it = 0; it < NST; it++) {
        if (it < NST - 1) CP_WAIT(1);
        else              CP_WAIT(0);
        __syncthreads();

        const __half* As = smem + (it & 1) * (2 * TILE_ELEMS);
        const __half* Bs = As + TILE_ELEMS;

        #pragma unroll
        for (int kk = 0; kk < BK / 16; kk++) {
            wmma::fragment<wmma::matrix_a, 16, 16, 16, __half, wmma::row_major> af[4];
            wmma::fragment<wmma::matrix_b, 16, 16, 16, __half, wmma::col_major> bf[4];
            #pragma unroll
            for (int i = 0; i < 4; i++)
                wmma::load_matrix_sync(af[i], As + (wr * 64 + i * 16) * LDSH + kk * 16, LDSH);
            #pragma unroll
            for (int j = 0; j < 4; j++)
                wmma::load_matrix_sync(bf[j], Bs + (wc * 64 + j * 16) * LDSH + kk * 16, LDSH);
            #pragma unroll
            for (int i = 0; i < 4; i++)
                #pragma unroll
                for (int j = 0; j < 4; j++)
                    wmma::mma_sync(acc[i][j], af[i], bf[j], acc[i][j]);
        }
        __syncthreads();     // all warps done reading this slot
        issue(it + 2);       // overwrites slot (it)&1 — safe post-sync
    }

    // -------- epilogue: 16x64 row bounce per m-frag, 128B-coalesced stores --------
    __syncthreads();
    float* cbuf = reinterpret_cast<float*>(smem) + warp * (16 * 68);
    const int cb = c0 + wc * 64;
    #pragma unroll 1
    for (int i = 0; i < 4; i++) {
        #pragma unroll
        for (int j = 0; j < 4; j++)
            wmma::store_matrix_sync(cbuf + j * 16, acc[i][j], 68, wmma::mem_row_major);
        __syncwarp();
        int mb = b0 + wr * 64 + i * 16;
        #pragma unroll
        for (int e = 0; e < 32; e++) {
            int idx = lane + 32 * e;        // 0..1023
            int rr = idx >> 6, cc = idx & 63;
            int c = cb + cc;
            if (c < NUM_CLASSES)
                out[(size_t)(mb + rr) * NUM_CLASSES + c] = cbuf[rr * 68 + cc] + __ldg(base_b + c);
        }
        __syncwarp();
    }
}

// ---------------------------------------------------------------------------
extern "C" void kernel_launch(void* const* d_in, const int* in_sizes, int n_in,
                              void* d_out, int out_size)
{
    const float* x       = (const float*)d_in[0];
    const float* context = (const float*)d_in[1];
    const float* base_w  = (const float*)d_in[2];
    const float* base_b  = (const float*)d_in[3];
    const float* ctx_w   = (const float*)d_in[4];
    const float* ctx_b   = (const float*)d_in[5];
    const float* ln_g    = (const float*)d_in[6];
    const float* ln_b    = (const float*)d_in[7];
    const float* coeff_w = (const float*)d_in[8];
    const float* coeff_b = (const float*)d_in[9];
    const float* basis_A = (const float*)d_in[10];
    const float* basis_B = (const float*)d_in[11];
    float* out = (float*)d_out;
    (void)in_sizes; (void)n_in; (void)out_size;

    cudaFuncSetAttribute(prep_ctx, cudaFuncAttributeMaxDynamicSharedMemorySize, P_TOTAL * 4);
    prep_ctx<<<BATCH / 16, 256, P_TOTAL * 4>>>(x, context, ctx_w, ctx_b, ln_g, ln_b,
                                               coeff_w, coeff_b, basis_A);
    convert_x<<<(unsigned)(((size_t)BATCH * (KTOT / 8) + 255) / 256), 256>>>(x);
    convert_w<<<(unsigned)(((size_t)NUM_CLASSES * (KTOT / 8) + 255) / 256), 256>>>(base_w, basis_B);

    static_assert(SMEM_TOTAL == 73728, "smem layout");
    cudaFuncSetAttribute(main_gemm, cudaFuncAttributeMaxDynamicSharedMemorySize, SMEM_TOTAL);
    dim3 grid(BATCH / BM, (NUM_CLASSES + BN - 1) / BN);   // 16 x 393, m fastest
    main_gemm<<<grid, 128, SMEM_TOTAL>>>(base_b, out);
}

// round 8
// speedup vs baseline: 3.6193x; 3.6193x over previous
#include <cuda_runtime.h>
#include <cuda_fp16.h>
#include <mma.h>
#include <cstdint>

using namespace nvcuda;

#define D_MODEL     2048
#define NUM_CLASSES 50257
#define NB          8
#define RANK        4
#define HIDDEN      128
#define BATCH       2048
#define LN_EPS      1e-5f

#define KTOT   2112                 // 2048 (x|w) + 32 (LoRA u|Bt) + 32 zero pad
#define BK     64
#define NST    (KTOT / BK)          // 33 stages, single fp16 pass

#define BM 128
#define BN 128
#define LDSH 72                     // fp16 elems per smem row (144B)
#define STAGE_ELEMS (128 * LDSH)
#define STAGE_BYTES (STAGE_ELEMS * 2)       // 18432
#define SMEM_TOTAL  (2 * 2 * STAGE_BYTES)   // 73728 B -> 2 CTAs/SM

// prep_ctx dynamic smem layout (floats)
#define P_WSH   0
#define P_XSH   (128 * 129)
#define P_HSH   (P_XSH + 16 * 129)
#define P_YSH   (P_HSH + 16 * 128)
#define P_CSH   (P_YSH + 16 * 32)
#define P_ZSH   (P_CSH + 16 * 8)
#define P_TOTAL (P_ZSH + 16 * 4)

// ---------------- device scratch ----------------
__device__ float  g_u[BATCH * 32];
__device__ __half g_Xh[(size_t)BATCH       * KTOT];
__device__ __half g_Wh[(size_t)NUM_CLASSES * KTOT];

__device__ __forceinline__ uint32_t smem_u32(const void* p) {
    uint32_t a;
    asm("{ .reg .u64 t; cvta.to.shared.u64 t, %1; cvt.u32.u64 %0, t; }" : "=r"(a) : "l"(p));
    return a;
}
#define CP_ASYNC16(dst, src) \
    asm volatile("cp.async.cg.shared.global [%0], [%1], 16;" :: "r"(dst), "l"(src))
#define CP_COMMIT() asm volatile("cp.async.commit_group;" ::: "memory")
#define CP_WAIT(n)  asm volatile("cp.async.wait_group %0;" :: "n"(n) : "memory")

// ---------------------------------------------------------------------------
// prep_ctx (coalesced): ctx MLP -> LN -> GELU -> coeffs -> z -> u
// ---------------------------------------------------------------------------
__global__ __launch_bounds__(256) void prep_ctx(
    const float* __restrict__ x, const float* __restrict__ context,
    const float* __restrict__ ctx_w, const float* __restrict__ ctx_b,
    const float* __restrict__ ln_g, const float* __restrict__ ln_b,
    const float* __restrict__ coeff_w, const float* __restrict__ coeff_b,
    const float* __restrict__ basis_A)
{
    extern __shared__ float ps[];
    float* wsh = ps + P_WSH;
    float* xsh = ps + P_XSH;
    float* hsh = ps + P_HSH;
    float* ysh = ps + P_YSH;
    float* csh = ps + P_CSH;
    float* zsh = ps + P_ZSH;

    const int t  = threadIdx.x;
    const int r0 = blockIdx.x * 16;

    // Phase A: h0 = context @ ctx_w^T + ctx_b
    {
        const int hA    = t & 127;
        const int rhalf = t >> 7;
        float acc[8];
        #pragma unroll
        for (int r = 0; r < 8; r++) acc[r] = 0.f;

        #pragma unroll 1
        for (int kc = 0; kc < D_MODEL / 128; kc++) {
            #pragma unroll
            for (int i = 0; i < 16; i++) {
                int idx = t + 256 * i;
                int h = idx >> 5, kq = idx & 31;
                float4 v = *reinterpret_cast<const float4*>(
                    ctx_w + (size_t)h * D_MODEL + kc * 128 + kq * 4);
                float* d = wsh + h * 129 + kq * 4;
                d[0] = v.x; d[1] = v.y; d[2] = v.z; d[3] = v.w;
            }
            #pragma unroll
            for (int i = 0; i < 8; i++) {
                int idx = t + 256 * i;
                int r = idx >> 7, k = idx & 127;
                xsh[r * 129 + k] = context[(size_t)(r0 + r) * D_MODEL + kc * 128 + k];
            }
            __syncthreads();
            #pragma unroll 4
            for (int k = 0; k < 128; k++) {
                float w = wsh[hA * 129 + k];
                #pragma unroll
                for (int r = 0; r < 8; r++)
                    acc[r] += xsh[(rhalf * 8 + r) * 129 + k] * w;
            }
            __syncthreads();
        }
        float b = ctx_b[hA];
        #pragma unroll
        for (int r = 0; r < 8; r++)
            hsh[(rhalf * 8 + r) * 128 + hA] = acc[r] + b;
    }
    __syncthreads();

    // Phase B: LayerNorm + exact GELU
    {
        const int lane = t & 31, w = t >> 5;
        #pragma unroll
        for (int rr = 0; rr < 2; rr++) {
            int row = w * 2 + rr;
            float v[4]; float s = 0.f;
            #pragma unroll
            for (int j = 0; j < 4; j++) { v[j] = hsh[row * 128 + lane * 4 + j]; s += v[j]; }
            #pragma unroll
            for (int o = 16; o > 0; o >>= 1) s += __shfl_xor_sync(0xffffffffu, s, o);
            float mu = s * (1.0f / HIDDEN);
            float q = 0.f;
            #pragma unroll
            for (int j = 0; j < 4; j++) { float d = v[j] - mu; q += d * d; }
            #pragma unroll
            for (int o = 16; o > 0; o >>= 1) q += __shfl_xor_sync(0xffffffffu, q, o);
            float rstd = rsqrtf(q * (1.0f / HIDDEN) + LN_EPS);
            #pragma unroll
            for (int j = 0; j < 4; j++) {
                int c = lane * 4 + j;
                float hn = (v[j] - mu) * rstd * ln_g[c] + ln_b[c];
                hsh[row * 128 + c] = 0.5f * hn * (1.0f + erff(hn * 0.7071067811865475f));
            }
        }
    }
    __syncthreads();

    // Phase C: coeffs
    if (t < 128) {
        int row = t >> 3, n = t & 7;
        const float* wp = coeff_w + (size_t)n * HIDDEN;
        float acc = coeff_b[n];
        #pragma unroll 8
        for (int j = 0; j < HIDDEN; j++) acc += hsh[row * 128 + j] * wp[j];
        csh[row * 8 + n] = acc;
    }
    __syncthreads();

    // Phase D: y = x @ basis_A^T
    {
        const int ka = t & 31;
        const int rq = t >> 5;
        float acc0 = 0.f, acc1 = 0.f;

        #pragma unroll 1
        for (int kc = 0; kc < D_MODEL / 128; kc++) {
            #pragma unroll
            for (int i = 0; i < 4; i++) {
                int idx = t + 256 * i;
                int a = idx >> 5, kq = idx & 31;
                float4 v = *reinterpret_cast<const float4*>(
                    basis_A + (size_t)a * D_MODEL + kc * 128 + kq * 4);
                float* d = wsh + a * 129 + kq * 4;
                d[0] = v.x; d[1] = v.y; d[2] = v.z; d[3] = v.w;
            }
            #pragma unroll
            for (int i = 0; i < 8; i++) {
                int idx = t + 256 * i;
                int r = idx >> 7, k = idx & 127;
                xsh[r * 129 + k] = x[(size_t)(r0 + r) * D_MODEL + kc * 128 + k];
            }
            __syncthreads();
            #pragma unroll 4
            for (int k = 0; k < 128; k++) {
                float a = wsh[ka * 129 + k];
                acc0 += xsh[(rq * 2 + 0) * 129 + k] * a;
                acc1 += xsh[(rq * 2 + 1) * 129 + k] * a;
            }
            __syncthreads();
        }
        ysh[(rq * 2 + 0) * 32 + ka] = acc0;
        ysh[(rq * 2 + 1) * 32 + ka] = acc1;
    }
    __syncthreads();

    // Phase E: z
    if (t < 64) {
        int row = t >> 2, r = t & 3;
        float acc = 0.f;
        #pragma unroll
        for (int n = 0; n < NB; n++) acc += csh[row * 8 + n] * ysh[row * 32 + n * RANK + r];
        zsh[row * 4 + r] = acc;
    }
    __syncthreads();

    // Phase F: u
    #pragma unroll
    for (int i = 0; i < 2; i++) {
        int idx = t + 256 * i;
        int row = idx >> 5, k = idx & 31;
        g_u[(size_t)(r0 + row) * 32 + k] = csh[row * 8 + (k >> 2)] * zsh[row * 4 + (k & 3)];
    }
}

// ---------------------------------------------------------------------------
__global__ __launch_bounds__(256) void convert_x(const float* __restrict__ x)
{
    size_t i = (size_t)blockIdx.x * 256 + threadIdx.x;
    if (i >= (size_t)BATCH * (KTOT / 8)) return;
    int row = (int)(i / (KTOT / 8));
    int k0  = (int)(i % (KTOT / 8)) * 8;

    float v[8];
    if (k0 < D_MODEL) {
        const float4* p = reinterpret_cast<const float4*>(x + (size_t)row * D_MODEL + k0);
        float4 a = p[0], b = p[1];
        v[0]=a.x; v[1]=a.y; v[2]=a.z; v[3]=a.w; v[4]=b.x; v[5]=b.y; v[6]=b.z; v[7]=b.w;
    } else if (k0 < D_MODEL + 32) {
        #pragma unroll
        for (int j = 0; j < 8; j++) v[j] = g_u[(size_t)row * 32 + (k0 - D_MODEL) + j];
    } else {
        #pragma unroll
        for (int j = 0; j < 8; j++) v[j] = 0.f;
    }
    union { __half h[8]; uint4 u; } H;
    #pragma unroll
    for (int j = 0; j < 8; j++) H.h[j] = __float2half_rn(v[j]);
    *reinterpret_cast<uint4*>(&g_Xh[(size_t)row * KTOT + k0]) = H.u;
}

__global__ __launch_bounds__(256) void convert_w(
    const float* __restrict__ base_w, const float* __restrict__ basis_B)
{
    size_t i = (size_t)blockIdx.x * 256 + threadIdx.x;
    if (i >= (size_t)NUM_CLASSES * (KTOT / 8)) return;
    int row = (int)(i / (KTOT / 8));
    int k0  = (int)(i % (KTOT / 8)) * 8;

    float v[8];
    if (k0 < D_MODEL) {
        const float4* p = reinterpret_cast<const float4*>(base_w + (size_t)row * D_MODEL + k0);
        float4 a = p[0], b = p[1];
        v[0]=a.x; v[1]=a.y; v[2]=a.z; v[3]=a.w; v[4]=b.x; v[5]=b.y; v[6]=b.z; v[7]=b.w;
    } else if (k0 < D_MODEL + 32) {
        #pragma unroll
        for (int j = 0; j < 8; j++) {
            int k = (k0 - D_MODEL) + j;      // n*RANK + r
            v[j] = basis_B[(((size_t)(k >> 2)) * NUM_CLASSES + row) * RANK + (k & 3)];
        }
    } else {
        #pragma unroll
        for (int j = 0; j < 8; j++) v[j] = 0.f;
    }
    union { __half h[8]; uint4 u; } H;
    #pragma unroll
    for (int j = 0; j < 8; j++) H.h[j] = __float2half_rn(v[j]);
    *reinterpret_cast<uint4*>(&g_Wh[(size_t)row * KTOT + k0]) = H.u;
}

// ---------------------------------------------------------------------------
// Main GEMM (R4-proven): out[b][c] = Xh[b]·Wh[c] + base_b[c]
// 128x128 tile, 8 warps (64x32 warp tiles), BK=64, 2-stage cp.async pipeline.
// ---------------------------------------------------------------------------
__global__ __launch_bounds__(256, 2) void main_gemm(
    const float* __restrict__ base_b, float* __restrict__ out)
{
    extern __shared__ __align__(128) __half smem[];
    const uint32_t sbase = smem_u32(smem);

    const int t    = threadIdx.x;
    const int warp = t >> 5;
    const int lane = t & 31;
    const int b0   = blockIdx.x * BM;
    const int c0   = blockIdx.y * BN;

    const int wr = warp >> 2;   // 0..1 (64 rows)
    const int wc = warp & 3;    // 0..3 (32 cols)

    auto issue = [&](int s) {
        if (s >= NST) return;
        int k0 = s * BK;
        const __half* Ag = g_Xh + (size_t)b0 * KTOT + k0;
        int slot = s & 1;
        uint32_t abase = sbase + slot * (2 * STAGE_BYTES);
        uint32_t bbase = abase + STAGE_BYTES;
        #pragma unroll
        for (int i = 0; i < 4; i++) {
            int idx = t + 256 * i;       // 0..1023
            int r = idx >> 3, c = idx & 7;
            CP_ASYNC16(abase + (uint32_t)(r * LDSH + c * 8) * 2,
                       Ag + (size_t)r * KTOT + c * 8);
            int gr = c0 + r; if (gr > NUM_CLASSES - 1) gr = NUM_CLASSES - 1;
            CP_ASYNC16(bbase + (uint32_t)(r * LDSH + c * 8) * 2,
                       g_Wh + (size_t)gr * KTOT + k0 + c * 8);
        }
        CP_COMMIT();
    };

    wmma::fragment<wmma::accumulator, 16, 16, 16, float> acc[4][2];
    #pragma unroll
    for (int i = 0; i < 4; i++)
        #pragma unroll
        for (int j = 0; j < 2; j++)
            wmma::fill_fragment(acc[i][j], 0.0f);

    issue(0); issue(1);

    #pragma unroll 1
    for (int it = 0; it < NST; it++) {
        if (it < NST - 1) CP_WAIT(1);
        else              CP_WAIT(0);
        __syncthreads();

        const __half* As = smem + (it & 1) * (2 * STAGE_ELEMS);
        const __half* Bs = As + STAGE_ELEMS;

        #pragma unroll
        for (int kk = 0; kk < BK / 16; kk++) {
            wmma::fragment<wmma::matrix_b, 16, 16, 16, __half, wmma::col_major> bf[2];
            #pragma unroll
            for (int j = 0; j < 2; j++)
                wmma::load_matrix_sync(bf[j], Bs + (wc * 32 + j * 16) * LDSH + kk * 16, LDSH);
            #pragma unroll
            for (int i = 0; i < 4; i++) {
                wmma::fragment<wmma::matrix_a, 16, 16, 16, __half, wmma::row_major> af;
                wmma::load_matrix_sync(af, As + (wr * 64 + i * 16) * LDSH + kk * 16, LDSH);
                #pragma unroll
                for (int j = 0; j < 2; j++)
                    wmma::mma_sync(acc[i][j], af, bf[j], acc[i][j]);
            }
        }
        __syncthreads();   // everyone done reading slot before overwriting it
        issue(it + 2);
    }

    // -------- epilogue: frag -> smem bounce -> coalesced fp32 store + bias --------
    __syncthreads();
    float* cbuf = reinterpret_cast<float*>(smem) + warp * (16 * 20);
    #pragma unroll
    for (int i = 0; i < 4; i++) {
        #pragma unroll
        for (int j = 0; j < 2; j++) {
            wmma::store_matrix_sync(cbuf, acc[i][j], 20, wmma::mem_row_major);
            __syncwarp();
            int mb = b0 + wr * 64 + i * 16;
            int cb = c0 + wc * 32 + j * 16;
            #pragma unroll
            for (int e = 0; e < 8; e++) {
                int idx = lane + 32 * e;     // 0..255
                int rr = idx >> 4, cc = idx & 15;
                int c = cb + cc;
                if (c < NUM_CLASSES)
                    out[(size_t)(mb + rr) * NUM_CLASSES + c] = cbuf[rr * 20 + cc] + __ldg(base_b + c);
            }
            __syncwarp();
        }
    }
}

// ---------------------------------------------------------------------------
extern "C" void kernel_launch(void* const* d_in, const int* in_sizes, int n_in,
                              void* d_out, int out_size)
{
    const float* x       = (const float*)d_in[0];
    const float* context = (const float*)d_in[1];
    const float* base_w  = (const float*)d_in[2];
    const float* base_b  = (const float*)d_in[3];
    const float* ctx_w   = (const float*)d_in[4];
    const float* ctx_b   = (const float*)d_in[5];
    const float* ln_g    = (const float*)d_in[6];
    const float* ln_b    = (const float*)d_in[7];
    const float* coeff_w = (const float*)d_in[8];
    const float* coeff_b = (const float*)d_in[9];
    const float* basis_A = (const float*)d_in[10];
    const float* basis_B = (const float*)d_in[11];
    float* out = (float*)d_out;
    (void)in_sizes; (void)n_in; (void)out_size;

    cudaFuncSetAttribute(prep_ctx, cudaFuncAttributeMaxDynamicSharedMemorySize, P_TOTAL * 4);
    prep_ctx<<<BATCH / 16, 256, P_TOTAL * 4>>>(x, context, ctx_w, ctx_b, ln_g, ln_b,
                                               coeff_w, coeff_b, basis_A);
    convert_x<<<(unsigned)(((size_t)BATCH * (KTOT / 8) + 255) / 256), 256>>>(x);
    convert_w<<<(unsigned)(((size_t)NUM_CLASSES * (KTOT / 8) + 255) / 256), 256>>>(base_w, basis_B);

    static_assert(SMEM_TOTAL == 73728, "smem layout");
    cudaFuncSetAttribute(main_gemm, cudaFuncAttributeMaxDynamicSharedMemorySize, SMEM_TOTAL);
    dim3 grid(BATCH / BM, (NUM_CLASSES + BN - 1) / BN);   // 16 x 393, m fastest
    main_gemm<<<grid, 256, SMEM_TOTAL>>>(base_b, out);
}

// round 10
// speedup vs baseline: 5.3297x; 1.4726x over previous
#include <cuda_runtime.h>
#include <cuda_fp16.h>
#include <mma.h>
#include <cstdint>

using namespace nvcuda;

#define D_MODEL     2048
#define NUM_CLASSES 50257
#define NB          8
#define RANK        4
#define HIDDEN      128
#define BATCH       2048
#define LN_EPS      1e-5f

#define KTOT   2112                 // 2048 (x|w) + 32 (LoRA u|Bt) + 32 zero pad
#define BK     64
#define NST    (KTOT / BK)          // 33 stages, single fp16 pass

#define BM 128
#define BN 128
#define LDSH 72                     // fp16 elems per smem row (144B)
#define STAGE_ELEMS (128 * LDSH)
#define STAGE_BYTES (STAGE_ELEMS * 2)       // 18432 per tile
#define SLOT_BYTES  (2 * STAGE_BYTES)       // A+B per slot = 36864
#define SMEM_TOTAL  (3 * SLOT_BYTES)        // 110592 B -> 2 CTAs/SM (verified R3)

// prep_ctx dynamic smem layout (floats)
#define P_WSH   0
#define P_XSH   (128 * 129)
#define P_HSH   (P_XSH + 16 * 129)
#define P_YSH   (P_HSH + 16 * 128)
#define P_CSH   (P_YSH + 16 * 32)
#define P_ZSH   (P_CSH + 16 * 8)
#define P_TOTAL (P_ZSH + 16 * 4)

// ---------------- device scratch ----------------
__device__ float  g_u[BATCH * 32];
__device__ __half g_Xh[(size_t)BATCH       * KTOT];
__device__ __half g_Wh[(size_t)NUM_CLASSES * KTOT];

__device__ __forceinline__ uint32_t smem_u32(const void* p) {
    uint32_t a;
    asm("{ .reg .u64 t; cvta.to.shared.u64 t, %1; cvt.u32.u64 %0, t; }" : "=r"(a) : "l"(p));
    return a;
}
#define CP_ASYNC16(dst, src) \
    asm volatile("cp.async.cg.shared.global [%0], [%1], 16;" :: "r"(dst), "l"(src))
#define CP_COMMIT() asm volatile("cp.async.commit_group;" ::: "memory")
#define CP_WAIT(n)  asm volatile("cp.async.wait_group %0;" :: "n"(n) : "memory")

// ---------------------------------------------------------------------------
// prep_ctx (coalesced): ctx MLP -> LN -> GELU -> coeffs -> z -> u
// ---------------------------------------------------------------------------
__global__ __launch_bounds__(256) void prep_ctx(
    const float* __restrict__ x, const float* __restrict__ context,
    const float* __restrict__ ctx_w, const float* __restrict__ ctx_b,
    const float* __restrict__ ln_g, const float* __restrict__ ln_b,
    const float* __restrict__ coeff_w, const float* __restrict__ coeff_b,
    const float* __restrict__ basis_A)
{
    extern __shared__ float ps[];
    float* wsh = ps + P_WSH;
    float* xsh = ps + P_XSH;
    float* hsh = ps + P_HSH;
    float* ysh = ps + P_YSH;
    float* csh = ps + P_CSH;
    float* zsh = ps + P_ZSH;

    const int t  = threadIdx.x;
    const int r0 = blockIdx.x * 16;

    // Phase A: h0 = context @ ctx_w^T + ctx_b
    {
        const int hA    = t & 127;
        const int rhalf = t >> 7;
        float acc[8];
        #pragma unroll
        for (int r = 0; r < 8; r++) acc[r] = 0.f;

        #pragma unroll 1
        for (int kc = 0; kc < D_MODEL / 128; kc++) {
            #pragma unroll
            for (int i = 0; i < 16; i++) {
                int idx = t + 256 * i;
                int h = idx >> 5, kq = idx & 31;
                float4 v = *reinterpret_cast<const float4*>(
                    ctx_w + (size_t)h * D_MODEL + kc * 128 + kq * 4);
                float* d = wsh + h * 129 + kq * 4;
                d[0] = v.x; d[1] = v.y; d[2] = v.z; d[3] = v.w;
            }
            #pragma unroll
            for (int i = 0; i < 8; i++) {
                int idx = t + 256 * i;
                int r = idx >> 7, k = idx & 127;
                xsh[r * 129 + k] = context[(size_t)(r0 + r) * D_MODEL + kc * 128 + k];
            }
            __syncthreads();
            #pragma unroll 4
            for (int k = 0; k < 128; k++) {
                float w = wsh[hA * 129 + k];
                #pragma unroll
                for (int r = 0; r < 8; r++)
                    acc[r] += xsh[(rhalf * 8 + r) * 129 + k] * w;
            }
            __syncthreads();
        }
        float b = ctx_b[hA];
        #pragma unroll
        for (int r = 0; r < 8; r++)
            hsh[(rhalf * 8 + r) * 128 + hA] = acc[r] + b;
    }
    __syncthreads();

    // Phase B: LayerNorm + exact GELU
    {
        const int lane = t & 31, w = t >> 5;
        #pragma unroll
        for (int rr = 0; rr < 2; rr++) {
            int row = w * 2 + rr;
            float v[4]; float s = 0.f;
            #pragma unroll
            for (int j = 0; j < 4; j++) { v[j] = hsh[row * 128 + lane * 4 + j]; s += v[j]; }
            #pragma unroll
            for (int o = 16; o > 0; o >>= 1) s += __shfl_xor_sync(0xffffffffu, s, o);
            float mu = s * (1.0f / HIDDEN);
            float q = 0.f;
            #pragma unroll
            for (int j = 0; j < 4; j++) { float d = v[j] - mu; q += d * d; }
            #pragma unroll
            for (int o = 16; o > 0; o >>= 1) q += __shfl_xor_sync(0xffffffffu, q, o);
            float rstd = rsqrtf(q * (1.0f / HIDDEN) + LN_EPS);
            #pragma unroll
            for (int j = 0; j < 4; j++) {
                int c = lane * 4 + j;
                float hn = (v[j] - mu) * rstd * ln_g[c] + ln_b[c];
                hsh[row * 128 + c] = 0.5f * hn * (1.0f + erff(hn * 0.7071067811865475f));
            }
        }
    }
    __syncthreads();

    // Phase C: coeffs
    if (t < 128) {
        int row = t >> 3, n = t & 7;
        const float* wp = coeff_w + (size_t)n * HIDDEN;
        float acc = coeff_b[n];
        #pragma unroll 8
        for (int j = 0; j < HIDDEN; j++) acc += hsh[row * 128 + j] * wp[j];
        csh[row * 8 + n] = acc;
    }
    __syncthreads();

    // Phase D: y = x @ basis_A^T
    {
        const int ka = t & 31;
        const int rq = t >> 5;
        float acc0 = 0.f, acc1 = 0.f;

        #pragma unroll 1
        for (int kc = 0; kc < D_MODEL / 128; kc++) {
            #pragma unroll
            for (int i = 0; i < 4; i++) {
                int idx = t + 256 * i;
                int a = idx >> 5, kq = idx & 31;
                float4 v = *reinterpret_cast<const float4*>(
                    basis_A + (size_t)a * D_MODEL + kc * 128 + kq * 4);
                float* d = wsh + a * 129 + kq * 4;
                d[0] = v.x; d[1] = v.y; d[2] = v.z; d[3] = v.w;
            }
            #pragma unroll
            for (int i = 0; i < 8; i++) {
                int idx = t + 256 * i;
                int r = idx >> 7, k = idx & 127;
                xsh[r * 129 + k] = x[(size_t)(r0 + r) * D_MODEL + kc * 128 + k];
            }
            __syncthreads();
            #pragma unroll 4
            for (int k = 0; k < 128; k++) {
                float a = wsh[ka * 129 + k];
                acc0 += xsh[(rq * 2 + 0) * 129 + k] * a;
                acc1 += xsh[(rq * 2 + 1) * 129 + k] * a;
            }
            __syncthreads();
        }
        ysh[(rq * 2 + 0) * 32 + ka] = acc0;
        ysh[(rq * 2 + 1) * 32 + ka] = acc1;
    }
    __syncthreads();

    // Phase E: z
    if (t < 64) {
        int row = t >> 2, r = t & 3;
        float acc = 0.f;
        #pragma unroll
        for (int n = 0; n < NB; n++) acc += csh[row * 8 + n] * ysh[row * 32 + n * RANK + r];
        zsh[row * 4 + r] = acc;
    }
    __syncthreads();

    // Phase F: u
    #pragma unroll
    for (int i = 0; i < 2; i++) {
        int idx = t + 256 * i;
        int row = idx >> 5, k = idx & 31;
        g_u[(size_t)(r0 + row) * 32 + k] = csh[row * 8 + (k >> 2)] * zsh[row * 4 + (k & 3)];
    }
}

// ---------------------------------------------------------------------------
__global__ __launch_bounds__(256) void convert_x(const float* __restrict__ x)
{
    size_t i = (size_t)blockIdx.x * 256 + threadIdx.x;
    if (i >= (size_t)BATCH * (KTOT / 8)) return;
    int row = (int)(i / (KTOT / 8));
    int k0  = (int)(i % (KTOT / 8)) * 8;

    float v[8];
    if (k0 < D_MODEL) {
        const float4* p = reinterpret_cast<const float4*>(x + (size_t)row * D_MODEL + k0);
        float4 a = p[0], b = p[1];
        v[0]=a.x; v[1]=a.y; v[2]=a.z; v[3]=a.w; v[4]=b.x; v[5]=b.y; v[6]=b.z; v[7]=b.w;
    } else if (k0 < D_MODEL + 32) {
        #pragma unroll
        for (int j = 0; j < 8; j++) v[j] = g_u[(size_t)row * 32 + (k0 - D_MODEL) + j];
    } else {
        #pragma unroll
        for (int j = 0; j < 8; j++) v[j] = 0.f;
    }
    union { __half h[8]; uint4 u; } H;
    #pragma unroll
    for (int j = 0; j < 8; j++) H.h[j] = __float2half_rn(v[j]);
    *reinterpret_cast<uint4*>(&g_Xh[(size_t)row * KTOT + k0]) = H.u;
}

__global__ __launch_bounds__(256) void convert_w(
    const float* __restrict__ base_w, const float* __restrict__ basis_B)
{
    size_t i = (size_t)blockIdx.x * 256 + threadIdx.x;
    if (i >= (size_t)NUM_CLASSES * (KTOT / 8)) return;
    int row = (int)(i / (KTOT / 8));
    int k0  = (int)(i % (KTOT / 8)) * 8;

    float v[8];
    if (k0 < D_MODEL) {
        const float4* p = reinterpret_cast<const float4*>(base_w + (size_t)row * D_MODEL + k0);
        float4 a = p[0], b = p[1];
        v[0]=a.x; v[1]=a.y; v[2]=a.z; v[3]=a.w; v[4]=b.x; v[5]=b.y; v[6]=b.z; v[7]=b.w;
    } else if (k0 < D_MODEL + 32) {
        #pragma unroll
        for (int j = 0; j < 8; j++) {
            int k = (k0 - D_MODEL) + j;      // n*RANK + r
            v[j] = basis_B[(((size_t)(k >> 2)) * NUM_CLASSES + row) * RANK + (k & 3)];
        }
    } else {
        #pragma unroll
        for (int j = 0; j < 8; j++) v[j] = 0.f;
    }
    union { __half h[8]; uint4 u; } H;
    #pragma unroll
    for (int j = 0; j < 8; j++) H.h[j] = __float2half_rn(v[j]);
    *reinterpret_cast<uint4*>(&g_Wh[(size_t)row * KTOT + k0]) = H.u;
}

// ---------------------------------------------------------------------------
// Main GEMM: out[b][c] = Xh[b]·Wh[c] + base_b[c]
// 128x128 tile, 8 warps (64x32), BK=64, 3-slot cp.async pipeline,
// ONE __syncthreads per stage, compute-before-issue order preserved:
//   top sync of iter `it` fences all readers of slot (it-1)%3;
//   issue(it+2) after compute targets exactly that slot.
// ---------------------------------------------------------------------------
__global__ __launch_bounds__(256, 2) void main_gemm(
    const float* __restrict__ base_b, float* __restrict__ out)
{
    extern __shared__ __align__(128) __half smem[];
    const uint32_t sbase = smem_u32(smem);

    const int t    = threadIdx.x;
    const int warp = t >> 5;
    const int lane = t & 31;
    const int b0   = blockIdx.x * BM;
    const int c0   = blockIdx.y * BN;

    const int wr = warp >> 2;   // 0..1 (64 rows)
    const int wc = warp & 3;    // 0..3 (32 cols)

    auto issue = [&](int s, int slot) {
        if (s >= NST) return;
        int k0 = s * BK;
        const __half* Ag = g_Xh + (size_t)b0 * KTOT + k0;
        uint32_t abase = sbase + (uint32_t)slot * SLOT_BYTES;
        uint32_t bbase = abase + STAGE_BYTES;
        #pragma unroll
        for (int i = 0; i < 4; i++) {
            int idx = t + 256 * i;       // 0..1023
            int r = idx >> 3, c = idx & 7;
            CP_ASYNC16(abase + (uint32_t)(r * LDSH + c * 8) * 2,
                       Ag + (size_t)r * KTOT + c * 8);
            int gr = c0 + r; if (gr > NUM_CLASSES - 1) gr = NUM_CLASSES - 1;
            CP_ASYNC16(bbase + (uint32_t)(r * LDSH + c * 8) * 2,
                       g_Wh + (size_t)gr * KTOT + k0 + c * 8);
        }
        CP_COMMIT();
    };

    wmma::fragment<wmma::accumulator, 16, 16, 16, float> acc[4][2];
    #pragma unroll
    for (int i = 0; i < 4; i++)
        #pragma unroll
        for (int j = 0; j < 2; j++)
            wmma::fill_fragment(acc[i][j], 0.0f);

    issue(0, 0); issue(1, 1);

    int cs = 0;   // compute slot = it % 3
    #pragma unroll 1
    for (int it = 0; it < NST; it++) {
        if (it < NST - 1) CP_WAIT(1);   // group `it` complete
        else              CP_WAIT(0);
        __syncthreads();                // fences readers of slot (it-1)%3

        const __half* As = smem + cs * (2 * STAGE_ELEMS);
        const __half* Bs = As + STAGE_ELEMS;

        #pragma unroll
        for (int kk = 0; kk < BK / 16; kk++) {
            wmma::fragment<wmma::matrix_b, 16, 16, 16, __half, wmma::col_major> bf[2];
            #pragma unroll
            for (int j = 0; j < 2; j++)
                wmma::load_matrix_sync(bf[j], Bs + (wc * 32 + j * 16) * LDSH + kk * 16, LDSH);
            #pragma unroll
            for (int i = 0; i < 4; i++) {
                wmma::fragment<wmma::matrix_a, 16, 16, 16, __half, wmma::row_major> af;
                wmma::load_matrix_sync(af, As + (wr * 64 + i * 16) * LDSH + kk * 16, LDSH);
                #pragma unroll
                for (int j = 0; j < 2; j++)
                    wmma::mma_sync(acc[i][j], af, bf[j], acc[i][j]);
            }
        }

        int is = cs + 2; if (is >= 3) is -= 3;   // (it+2)%3 == (it-1)%3
        issue(it + 2, is);                       // safe: readers fenced at top sync
        cs = (cs == 2) ? 0 : cs + 1;
    }

    // -------- epilogue: frag -> smem bounce -> coalesced fp32 store + bias --------
    __syncthreads();
    float* cbuf = reinterpret_cast<float*>(smem) + warp * (16 * 20);
    #pragma unroll
    for (int i = 0; i < 4; i++) {
        #pragma unroll
        for (int j = 0; j < 2; j++) {
            wmma::store_matrix_sync(cbuf, acc[i][j], 20, wmma::mem_row_major);
            __syncwarp();
            int mb = b0 + wr * 64 + i * 16;
            int cb = c0 + wc * 32 + j * 16;
            int c_lane = cb + (lane & 15);
            float bias = (c_lane < NUM_CLASSES) ? __ldg(base_b + c_lane) : 0.f;
            #pragma unroll
            for (int e = 0; e < 8; e++) {
                int idx = lane + 32 * e;     // 0..255
                int rr = idx >> 4, cc = idx & 15;
                int c = cb + cc;
                float bv = __shfl_sync(0xffffffffu, bias, (idx & 15) + (lane & 16));
                // simpler correct path: reload if shuffle mapping mismatched
                if (c < NUM_CLASSES)
                    out[(size_t)(mb + rr) * NUM_CLASSES + c] = cbuf[rr * 20 + cc] + __ldg(base_b + c);
                (void)bv;
            }
            __syncwarp();
        }
    }
}

// ---------------------------------------------------------------------------
extern "C" void kernel_launch(void* const* d_in, const int* in_sizes, int n_in,
                              void* d_out, int out_size)
{
    const float* x       = (const float*)d_in[0];
    const float* context = (const float*)d_in[1];
    const float* base_w  = (const float*)d_in[2];
    const float* base_b  = (const float*)d_in[3];
    const float* ctx_w   = (const float*)d_in[4];
    const float* ctx_b   = (const float*)d_in[5];
    const float* ln_g    = (const float*)d_in[6];
    const float* ln_b    = (const float*)d_in[7];
    const float* coeff_w = (const float*)d_in[8];
    const float* coeff_b = (const float*)d_in[9];
    const float* basis_A = (const float*)d_in[10];
    const float* basis_B = (const float*)d_in[11];
    float* out = (float*)d_out;
    (void)in_sizes; (void)n_in; (void)out_size;

    cudaFuncSetAttribute(prep_ctx, cudaFuncAttributeMaxDynamicSharedMemorySize, P_TOTAL * 4);
    prep_ctx<<<BATCH / 16, 256, P_TOTAL * 4>>>(x, context, ctx_w, ctx_b, ln_g, ln_b,
                                               coeff_w, coeff_b, basis_A);
    convert_x<<<(unsigned)(((size_t)BATCH * (KTOT / 8) + 255) / 256), 256>>>(x);
    convert_w<<<(unsigned)(((size_t)NUM_CLASSES * (KTOT / 8) + 255) / 256), 256>>>(base_w, basis_B);

    static_assert(SMEM_TOTAL == 110592, "smem layout");
    cudaFuncSetAttribute(main_gemm, cudaFuncAttributeMaxDynamicSharedMemorySize, SMEM_TOTAL);
    dim3 grid(BATCH / BM, (NUM_CLASSES + BN - 1) / BN);   // 16 x 393, m fastest
    main_gemm<<<grid, 256, SMEM_TOTAL>>>(base_b, out);
}